// round 4
// baseline (speedup 1.0000x reference)
#include <cuda_runtime.h>
#include <math_constants.h>

// Density-aware Chamfer loss, B=4, N=8192, 3D fp32.
//  nn_kernel        : 1024-ref slice in 16KB smem (broadcast LDS); packed
//                     fma.rn.f32x2 over j-pairs, QPT=4; group-min (32) +
//                     winning-group bit-exact rescan => slice first-argmin.
//                     Also zeroes g_cnt. 512 CTAs, ~3 CTAs/SM.
//  merge_kernel     : strict-< merge over 8 slices, histogram atomics.
//  finalize_partial : 64-block gather/exp/weight partial sums
//  finalize_final   : fixed-order merge -> out[b]

#define B_CONST   4
#define N_CONST   8192
#define TPB       256
#define QPT       4
#define QPC       (TPB * QPT)            // 1024 queries / CTA
#define QCHUNKS   (N_CONST / QPC)        // 8
#define RSLICES   8
#define RSLICE    (N_CONST / RSLICES)    // 1024 refs / slice
#define GROUP     32
#define JPG       (GROUP / 2)            // 16
#define NGROUPS   (RSLICE / GROUP)       // 32

#define FIN_TPB   256
#define FIN_EPB   1024
#define FIN_BLOCKS (2 * B_CONST * N_CONST / FIN_EPB)  // 64

__device__ float g_pbest[2 * B_CONST * RSLICES * N_CONST];
__device__ int   g_pidx [2 * B_CONST * RSLICES * N_CONST];
__device__ int   g_idx  [2 * B_CONST * N_CONST];
__device__ int   g_cnt  [2 * B_CONST * N_CONST];
__device__ float g_part [FIN_BLOCKS];

// db = dir*B + b.  dir 0: queries = gts, refs = preds. dir 1: swapped.
__global__ __launch_bounds__(TPB, 2) void nn_kernel(const float* __restrict__ gts,
                                                    const float* __restrict__ preds) {
    __shared__ float s_tile[RSLICE * 4];  // jj*8 -> rx0 rx1 ry0 ry1 rz0 rz1 rw0 rw1

    // ---- zero g_cnt (65536 entries; 512 CTAs x 256 thr = 131072 threads) ----
    {
        int flat = blockIdx.x + QCHUNKS * (blockIdx.y + RSLICES * blockIdx.z);
        int t = flat * TPB + threadIdx.x;
        if (t < 2 * B_CONST * N_CONST) g_cnt[t] = 0;
    }

    const int db  = blockIdx.z;
    const int b   = db & (B_CONST - 1);
    const int dir = db >> 2;
    const int s   = blockIdx.y;
    const float* __restrict__ qptr = (dir == 0) ? gts : preds;
    const float* __restrict__ rptr = (dir == 0) ? preds : gts;

    // ---- load ref slice into interleaved smem ----
    const float* rbase = rptr + ((long)b * N_CONST + (long)s * RSLICE) * 3;
    for (int j = threadIdx.x; j < RSLICE; j += TPB) {
        float x = rbase[3 * j + 0];
        float y = rbase[3 * j + 1];
        float z = rbase[3 * j + 2];
        int jj = j >> 1, h = j & 1;
        float* p = s_tile + jj * 8;
        p[0 + h] = x;
        p[2 + h] = y;
        p[4 + h] = z;
        p[6 + h] = x * x + y * y + z * z;
    }
    __syncthreads();

    // ---- per-thread queries: packed-duplicated (-2*q) ----
    const int q0 = blockIdx.x * QPC + threadIdx.x;
    const float* qbase = qptr + (long)b * N_CONST * 3;

    unsigned long long qx2[QPT], qy2[QPT], qz2[QPT];
    float best[QPT];
    int   gidw[QPT];
    float minE[QPT], minO[QPT];

    #pragma unroll
    for (int k = 0; k < QPT; k++) {
        int q = q0 + k * TPB;
        float qx = -2.0f * qbase[3 * q + 0];
        float qy = -2.0f * qbase[3 * q + 1];
        float qz = -2.0f * qbase[3 * q + 2];
        asm("mov.b64 %0, {%1, %1};" : "=l"(qx2[k]) : "f"(qx));
        asm("mov.b64 %0, {%1, %1};" : "=l"(qy2[k]) : "f"(qy));
        asm("mov.b64 %0, {%1, %1};" : "=l"(qz2[k]) : "f"(qz));
        best[k] = CUDART_INF_F;
        gidw[k] = 0;
        minE[k] = CUDART_INF_F;
        minO[k] = CUDART_INF_F;
    }

    // ---- main scan: groups of 32 refs, packed over j-pairs ----
    for (int g = 0; g < NGROUPS; g++) {
        const float* gb = s_tile + g * JPG * 8;
        #pragma unroll 4
        for (int jj = 0; jj < JPG; jj++) {
            ulonglong2 A  = *(const ulonglong2*)(gb + jj * 8);      // {rx2, ry2}
            ulonglong2 Bv = *(const ulonglong2*)(gb + jj * 8 + 4);  // {rz2, rw2}
            #pragma unroll
            for (int k = 0; k < QPT; k++) {
                float tlo, thi;
                asm("{\n\t"
                    ".reg .b64 t;\n\t"
                    "fma.rn.f32x2 t, %2, %3, %4;\n\t"
                    "fma.rn.f32x2 t, %5, %6, t;\n\t"
                    "fma.rn.f32x2 t, %7, %8, t;\n\t"
                    "mov.b64 {%0, %1}, t;\n\t"
                    "}"
                    : "=f"(tlo), "=f"(thi)
                    : "l"(qx2[k]), "l"(A.x), "l"(Bv.y),
                      "l"(qy2[k]), "l"(A.y),
                      "l"(qz2[k]), "l"(Bv.x));
                minE[k] = fminf(minE[k], tlo);
                minO[k] = fminf(minO[k], thi);
            }
        }
        #pragma unroll
        for (int k = 0; k < QPT; k++) {
            float m = fminf(minE[k], minO[k]);
            if (m < best[k]) { best[k] = m; gidw[k] = g; }  // strict <: earliest group wins
            minE[k] = CUDART_INF_F;
            minO[k] = CUDART_INF_F;
        }
    }

    // ---- rescan winning group: bit-exact recompute, first index wins ----
    const long obase = ((long)db * RSLICES + s) * N_CONST;
    #pragma unroll
    for (int k = 0; k < QPT; k++) {
        float qx, qy, qz, dummy;
        asm("mov.b64 {%0, %1}, %2;" : "=f"(qx), "=f"(dummy) : "l"(qx2[k]));
        asm("mov.b64 {%0, %1}, %2;" : "=f"(qy), "=f"(dummy) : "l"(qy2[k]));
        asm("mov.b64 {%0, %1}, %2;" : "=f"(qz), "=f"(dummy) : "l"(qz2[k]));
        const int base = gidw[k] * GROUP;
        int idx = 0x7fffffff;
        #pragma unroll 8
        for (int j = 0; j < GROUP; j++) {
            int jj = (base + j) >> 1, h = (base + j) & 1;
            const float* p = s_tile + jj * 8;
            float t = fmaf(qx, p[0 + h], p[6 + h]);
            t = fmaf(qy, p[2 + h], t);
            t = fmaf(qz, p[4 + h], t);
            if (t == best[k]) idx = min(idx, base + j);
        }
        int q = q0 + k * TPB;
        g_pbest[obase + q] = best[k];
        g_pidx [obase + q] = s * RSLICE + idx;
    }
}

__global__ void merge_kernel() {
    int gid = blockIdx.x * blockDim.x + threadIdx.x;  // over 2*B*N
    if (gid >= 2 * B_CONST * N_CONST) return;
    const int db = gid / N_CONST;
    const int q  = gid - db * N_CONST;

    float best = CUDART_INF_F;
    int   bi   = 0;
    #pragma unroll
    for (int s = 0; s < RSLICES; s++) {
        long e = ((long)db * RSLICES + s) * N_CONST + q;
        float v = g_pbest[e];
        int  id = g_pidx[e];
        if (v < best) { best = v; bi = id; }   // ascending slices => first-min tie-break
    }
    g_idx[gid] = bi;
    atomicAdd(&g_cnt[db * N_CONST + bi], 1);
}

__global__ __launch_bounds__(FIN_TPB) void finalize_partial(const float* __restrict__ gts,
                                                            const float* __restrict__ preds) {
    __shared__ float ssum[FIN_TPB];
    float acc = 0.0f;
    const int e0 = blockIdx.x * FIN_EPB;

    #pragma unroll
    for (int i = 0; i < FIN_EPB / FIN_TPB; i++) {
        int e = e0 + i * FIN_TPB + threadIdx.x;
        int db = e / N_CONST;
        int q  = e - db * N_CONST;
        int b  = db & (B_CONST - 1);
        int dir = db >> 2;
        const float* qptr = (dir == 0) ? gts : preds;
        const float* rptr = (dir == 0) ? preds : gts;
        const float* qb = qptr + (long)b * N_CONST * 3;
        const float* rb = rptr + (long)b * N_CONST * 3;

        int id = g_idx[e];
        float dx = qb[3 * q + 0] - rb[3 * id + 0];
        float dy = qb[3 * q + 1] - rb[3 * id + 1];
        float dz = qb[3 * q + 2] - rb[3 * id + 2];
        float d  = dx * dx + dy * dy + dz * dz;
        float c  = (float)g_cnt[db * N_CONST + id];
        acc += 1.0f - expf(-d) / (c + 1e-6f);   // ALPHA=1, N_LAMBDA=1, frac=1
    }

    ssum[threadIdx.x] = acc;
    __syncthreads();
    for (int off = FIN_TPB / 2; off > 0; off >>= 1) {
        if (threadIdx.x < off) ssum[threadIdx.x] += ssum[threadIdx.x + off];
        __syncthreads();
    }
    if (threadIdx.x == 0) g_part[blockIdx.x] = ssum[0];
}

__global__ void finalize_final(float* __restrict__ out) {
    int b = threadIdx.x;
    if (b >= B_CONST) return;
    float s = 0.0f;
    #pragma unroll
    for (int dir = 0; dir < 2; dir++) {
        int db = dir * B_CONST + b;
        #pragma unroll
        for (int c = 0; c < N_CONST / FIN_EPB; c++)
            s += g_part[db * (N_CONST / FIN_EPB) + c];
    }
    out[b] = s / (2.0f * (float)N_CONST);
}

extern "C" void kernel_launch(void* const* d_in, const int* in_sizes, int n_in,
                              void* d_out, int out_size) {
    const float* gts   = (const float*)d_in[0];
    const float* preds = (const float*)d_in[1];
    float* out = (float*)d_out;

    nn_kernel<<<dim3(QCHUNKS, RSLICES, 2 * B_CONST), TPB>>>(gts, preds);
    merge_kernel<<<(2 * B_CONST * N_CONST + 255) / 256, 256>>>();
    finalize_partial<<<FIN_BLOCKS, FIN_TPB>>>(gts, preds);
    finalize_final<<<1, 32>>>(out);
}

// round 5
// speedup vs baseline: 1.3845x; 1.3845x over previous
#include <cuda_runtime.h>
#include <math_constants.h>

// Density-aware Chamfer loss, B=4, N=8192, 3D fp32.
// R2 skeleton (best known: whole ref cloud in 128KB smem, one pass, inline
// atomics, no merge kernel) with TPB=512 / QPT=1: 4 warps/SMSP instead of 2
// to cover the LDS->FMA->FMNMX dependency chain.
//  zero_kernel      : clear counts
//  nn_kernel        : packed fma.rn.f32x2 over j-pairs; group-min (32) +
//                     winning-group bit-exact rescan => global first-argmin;
//                     writes g_idx, histogram atomics inline.
//  finalize_partial : 64-block gather/exp/weight partial sums
//  finalize_final   : fixed-order merge -> out[b]

#define B_CONST   4
#define N_CONST   8192
#define TPB       512
#define QPT       1
#define QPC       (TPB * QPT)          // 512 queries / CTA
#define QCHUNKS   (N_CONST / QPC)      // 16
#define GROUP     32
#define JPG       (GROUP / 2)          // 16
#define NGROUPS   (N_CONST / GROUP)    // 256
#define SMEM_BYTES (N_CONST * 4 * sizeof(float))   // 131072

#define FIN_TPB   256
#define FIN_EPB   1024
#define FIN_BLOCKS (2 * B_CONST * N_CONST / FIN_EPB)  // 64

__device__ int   g_idx [2 * B_CONST * N_CONST];
__device__ int   g_cnt [2 * B_CONST * N_CONST];
__device__ float g_part[FIN_BLOCKS];

__global__ void zero_kernel() {
    int gid = blockIdx.x * blockDim.x + threadIdx.x;
    if (gid < 2 * B_CONST * N_CONST) g_cnt[gid] = 0;
}

// db = dir*B + b.  dir 0: queries = gts, refs = preds. dir 1: swapped.
__global__ __launch_bounds__(TPB, 1) void nn_kernel(const float* __restrict__ gts,
                                                    const float* __restrict__ preds) {
    extern __shared__ float s_tile[];   // jj*8 -> rx0 rx1 ry0 ry1 rz0 rz1 rw0 rw1

    const int db  = blockIdx.y;
    const int b   = db & (B_CONST - 1);
    const int dir = db >> 2;
    const float* __restrict__ qptr = (dir == 0) ? gts : preds;
    const float* __restrict__ rptr = (dir == 0) ? preds : gts;

    // ---- load whole ref cloud into interleaved smem ----
    const float* rbase = rptr + (long)b * N_CONST * 3;
    for (int j = threadIdx.x; j < N_CONST; j += TPB) {
        float x = rbase[3 * j + 0];
        float y = rbase[3 * j + 1];
        float z = rbase[3 * j + 2];
        int jj = j >> 1, h = j & 1;
        float* p = s_tile + jj * 8;
        p[0 + h] = x;
        p[2 + h] = y;
        p[4 + h] = z;
        p[6 + h] = x * x + y * y + z * z;
    }
    __syncthreads();

    // ---- one query per thread: packed-duplicated (-2*q) ----
    const int q = blockIdx.x * QPC + threadIdx.x;
    const float* qbase = qptr + (long)b * N_CONST * 3;

    const float qxs = -2.0f * qbase[3 * q + 0];
    const float qys = -2.0f * qbase[3 * q + 1];
    const float qzs = -2.0f * qbase[3 * q + 2];
    unsigned long long qx2, qy2, qz2;
    asm("mov.b64 %0, {%1, %1};" : "=l"(qx2) : "f"(qxs));
    asm("mov.b64 %0, {%1, %1};" : "=l"(qy2) : "f"(qys));
    asm("mov.b64 %0, {%1, %1};" : "=l"(qz2) : "f"(qzs));

    float best = CUDART_INF_F;
    int   gidw = 0;
    float minE = CUDART_INF_F, minO = CUDART_INF_F;

    // ---- main scan: groups of 32 refs, packed over j-pairs ----
    for (int g = 0; g < NGROUPS; g++) {
        const float* gb = s_tile + g * JPG * 8;
        #pragma unroll 8
        for (int jj = 0; jj < JPG; jj++) {
            ulonglong2 A  = *(const ulonglong2*)(gb + jj * 8);      // {rx2, ry2}
            ulonglong2 Bv = *(const ulonglong2*)(gb + jj * 8 + 4);  // {rz2, rw2}
            float tlo, thi;
            asm("{\n\t"
                ".reg .b64 t;\n\t"
                "fma.rn.f32x2 t, %2, %3, %4;\n\t"
                "fma.rn.f32x2 t, %5, %6, t;\n\t"
                "fma.rn.f32x2 t, %7, %8, t;\n\t"
                "mov.b64 {%0, %1}, t;\n\t"
                "}"
                : "=f"(tlo), "=f"(thi)
                : "l"(qx2), "l"(A.x), "l"(Bv.y),
                  "l"(qy2), "l"(A.y),
                  "l"(qz2), "l"(Bv.x));
            minE = fminf(minE, tlo);
            minO = fminf(minO, thi);
        }
        float m = fminf(minE, minO);
        if (m < best) { best = m; gidw = g; }  // strict <: earliest group wins
        minE = CUDART_INF_F;
        minO = CUDART_INF_F;
    }

    // ---- rescan winning group: bit-exact recompute, first index wins ----
    {
        const int base = gidw * GROUP;
        int idx = 0x7fffffff;
        #pragma unroll 8
        for (int j = 0; j < GROUP; j++) {
            int jj = (base + j) >> 1, h = (base + j) & 1;
            const float* p = s_tile + jj * 8;
            float t = fmaf(qxs, p[0 + h], p[6 + h]);
            t = fmaf(qys, p[2 + h], t);
            t = fmaf(qzs, p[4 + h], t);
            if (t == best) idx = min(idx, base + j);
        }
        g_idx[db * N_CONST + q] = idx;
        atomicAdd(&g_cnt[db * N_CONST + idx], 1);
    }
}

__global__ __launch_bounds__(FIN_TPB) void finalize_partial(const float* __restrict__ gts,
                                                            const float* __restrict__ preds) {
    __shared__ float ssum[FIN_TPB];
    float acc = 0.0f;
    const int e0 = blockIdx.x * FIN_EPB;

    #pragma unroll
    for (int i = 0; i < FIN_EPB / FIN_TPB; i++) {
        int e = e0 + i * FIN_TPB + threadIdx.x;
        int db = e / N_CONST;
        int q  = e - db * N_CONST;
        int b  = db & (B_CONST - 1);
        int dir = db >> 2;
        const float* qptr = (dir == 0) ? gts : preds;
        const float* rptr = (dir == 0) ? preds : gts;
        const float* qb = qptr + (long)b * N_CONST * 3;
        const float* rb = rptr + (long)b * N_CONST * 3;

        int id = g_idx[e];
        float dx = qb[3 * q + 0] - rb[3 * id + 0];
        float dy = qb[3 * q + 1] - rb[3 * id + 1];
        float dz = qb[3 * q + 2] - rb[3 * id + 2];
        float d  = dx * dx + dy * dy + dz * dz;
        float c  = (float)g_cnt[db * N_CONST + id];
        acc += 1.0f - expf(-d) / (c + 1e-6f);   // ALPHA=1, N_LAMBDA=1, frac=1
    }

    ssum[threadIdx.x] = acc;
    __syncthreads();
    for (int off = FIN_TPB / 2; off > 0; off >>= 1) {
        if (threadIdx.x < off) ssum[threadIdx.x] += ssum[threadIdx.x + off];
        __syncthreads();
    }
    if (threadIdx.x == 0) g_part[blockIdx.x] = ssum[0];
}

__global__ void finalize_final(float* __restrict__ out) {
    int b = threadIdx.x;
    if (b >= B_CONST) return;
    float s = 0.0f;
    #pragma unroll
    for (int dir = 0; dir < 2; dir++) {
        int db = dir * B_CONST + b;
        #pragma unroll
        for (int c = 0; c < N_CONST / FIN_EPB; c++)
            s += g_part[db * (N_CONST / FIN_EPB) + c];
    }
    out[b] = s / (2.0f * (float)N_CONST);
}

extern "C" void kernel_launch(void* const* d_in, const int* in_sizes, int n_in,
                              void* d_out, int out_size) {
    const float* gts   = (const float*)d_in[0];
    const float* preds = (const float*)d_in[1];
    float* out = (float*)d_out;

    cudaFuncSetAttribute(nn_kernel, cudaFuncAttributeMaxDynamicSharedMemorySize, SMEM_BYTES);

    zero_kernel<<<(2 * B_CONST * N_CONST + 255) / 256, 256>>>();
    nn_kernel<<<dim3(QCHUNKS, 2 * B_CONST), TPB, SMEM_BYTES>>>(gts, preds);
    finalize_partial<<<FIN_BLOCKS, FIN_TPB>>>(gts, preds);
    finalize_final<<<1, 32>>>(out);
}

// round 6
// speedup vs baseline: 1.5933x; 1.1508x over previous
#include <cuda_runtime.h>
#include <math_constants.h>

// Density-aware Chamfer loss, B=4, N=8192, 3D fp32.
// R2 skeleton with ONE change: refs split into 2 slices of 4096 (64KB smem)
// => 2 CTAs/SM, 16 warps/SM for stall coverage. Adds a cheap 2-way merge.
//  zero_kernel      : clear counts
//  nn_kernel        : 4096-ref slice in smem; packed fma.rn.f32x2, QPT=2,
//                     unroll 8; group-min (32) + winning-group bit-exact
//                     rescan => slice first-argmin -> g_pbest/g_pidx.
//  merge_kernel     : strict-< merge over 2 slices, histogram atomics.
//  finalize_partial : 64-block gather/exp/weight partial sums
//  finalize_final   : fixed-order merge -> out[b]

#define B_CONST   4
#define N_CONST   8192
#define TPB       256
#define QPT       2
#define QPC       (TPB * QPT)          // 512 queries / CTA
#define QCHUNKS   (N_CONST / QPC)      // 16
#define RSLICES   2
#define RSLICE    (N_CONST / RSLICES)  // 4096
#define GROUP     32
#define JPG       (GROUP / 2)          // 16
#define NGROUPS   (RSLICE / GROUP)     // 128
#define SMEM_BYTES (RSLICE * 4 * sizeof(float))   // 65536

#define FIN_TPB   256
#define FIN_EPB   1024
#define FIN_BLOCKS (2 * B_CONST * N_CONST / FIN_EPB)  // 64

__device__ float g_pbest[2 * B_CONST * RSLICES * N_CONST];
__device__ int   g_pidx [2 * B_CONST * RSLICES * N_CONST];
__device__ int   g_idx  [2 * B_CONST * N_CONST];
__device__ int   g_cnt  [2 * B_CONST * N_CONST];
__device__ float g_part [FIN_BLOCKS];

__global__ void zero_kernel() {
    int gid = blockIdx.x * blockDim.x + threadIdx.x;
    if (gid < 2 * B_CONST * N_CONST) g_cnt[gid] = 0;
}

// db = dir*B + b.  dir 0: queries = gts, refs = preds. dir 1: swapped.
__global__ __launch_bounds__(TPB, 2) void nn_kernel(const float* __restrict__ gts,
                                                    const float* __restrict__ preds) {
    extern __shared__ float s_tile[];   // jj*8 -> rx0 rx1 ry0 ry1 rz0 rz1 rw0 rw1

    const int db  = blockIdx.z;
    const int b   = db & (B_CONST - 1);
    const int dir = db >> 2;
    const int s   = blockIdx.y;
    const float* __restrict__ qptr = (dir == 0) ? gts : preds;
    const float* __restrict__ rptr = (dir == 0) ? preds : gts;

    // ---- load ref slice into interleaved smem ----
    const float* rbase = rptr + ((long)b * N_CONST + (long)s * RSLICE) * 3;
    for (int j = threadIdx.x; j < RSLICE; j += TPB) {
        float x = rbase[3 * j + 0];
        float y = rbase[3 * j + 1];
        float z = rbase[3 * j + 2];
        int jj = j >> 1, h = j & 1;
        float* p = s_tile + jj * 8;
        p[0 + h] = x;
        p[2 + h] = y;
        p[4 + h] = z;
        p[6 + h] = x * x + y * y + z * z;
    }
    __syncthreads();

    // ---- per-thread queries: packed-duplicated (-2*q) ----
    const int q0 = blockIdx.x * QPC + threadIdx.x;
    const float* qbase = qptr + (long)b * N_CONST * 3;

    float qxs[QPT], qys[QPT], qzs[QPT];
    unsigned long long qx2[QPT], qy2[QPT], qz2[QPT];
    float best[QPT];
    int   gidw[QPT];
    float minE[QPT], minO[QPT];

    #pragma unroll
    for (int k = 0; k < QPT; k++) {
        int q = q0 + k * TPB;
        qxs[k] = -2.0f * qbase[3 * q + 0];
        qys[k] = -2.0f * qbase[3 * q + 1];
        qzs[k] = -2.0f * qbase[3 * q + 2];
        asm("mov.b64 %0, {%1, %1};" : "=l"(qx2[k]) : "f"(qxs[k]));
        asm("mov.b64 %0, {%1, %1};" : "=l"(qy2[k]) : "f"(qys[k]));
        asm("mov.b64 %0, {%1, %1};" : "=l"(qz2[k]) : "f"(qzs[k]));
        best[k] = CUDART_INF_F;
        gidw[k] = 0;
        minE[k] = CUDART_INF_F;
        minO[k] = CUDART_INF_F;
    }

    // ---- main scan: groups of 32 refs, packed over j-pairs ----
    for (int g = 0; g < NGROUPS; g++) {
        const float* gb = s_tile + g * JPG * 8;
        #pragma unroll 8
        for (int jj = 0; jj < JPG; jj++) {
            ulonglong2 A  = *(const ulonglong2*)(gb + jj * 8);      // {rx2, ry2}
            ulonglong2 Bv = *(const ulonglong2*)(gb + jj * 8 + 4);  // {rz2, rw2}
            #pragma unroll
            for (int k = 0; k < QPT; k++) {
                float tlo, thi;
                asm("{\n\t"
                    ".reg .b64 t;\n\t"
                    "fma.rn.f32x2 t, %2, %3, %4;\n\t"
                    "fma.rn.f32x2 t, %5, %6, t;\n\t"
                    "fma.rn.f32x2 t, %7, %8, t;\n\t"
                    "mov.b64 {%0, %1}, t;\n\t"
                    "}"
                    : "=f"(tlo), "=f"(thi)
                    : "l"(qx2[k]), "l"(A.x), "l"(Bv.y),
                      "l"(qy2[k]), "l"(A.y),
                      "l"(qz2[k]), "l"(Bv.x));
                minE[k] = fminf(minE[k], tlo);
                minO[k] = fminf(minO[k], thi);
            }
        }
        #pragma unroll
        for (int k = 0; k < QPT; k++) {
            float m = fminf(minE[k], minO[k]);
            if (m < best[k]) { best[k] = m; gidw[k] = g; }  // strict <: earliest group wins
            minE[k] = CUDART_INF_F;
            minO[k] = CUDART_INF_F;
        }
    }

    // ---- rescan winning group: bit-exact recompute, first index wins ----
    const long obase = ((long)db * RSLICES + s) * N_CONST;
    #pragma unroll
    for (int k = 0; k < QPT; k++) {
        const int base = gidw[k] * GROUP;
        int idx = 0x7fffffff;
        #pragma unroll 8
        for (int j = 0; j < GROUP; j++) {
            int jj = (base + j) >> 1, h = (base + j) & 1;
            const float* p = s_tile + jj * 8;
            float t = fmaf(qxs[k], p[0 + h], p[6 + h]);
            t = fmaf(qys[k], p[2 + h], t);
            t = fmaf(qzs[k], p[4 + h], t);
            if (t == best[k]) idx = min(idx, base + j);
        }
        int q = q0 + k * TPB;
        g_pbest[obase + q] = best[k];
        g_pidx [obase + q] = s * RSLICE + idx;
    }
}

__global__ void merge_kernel() {
    int gid = blockIdx.x * blockDim.x + threadIdx.x;  // over 2*B*N
    if (gid >= 2 * B_CONST * N_CONST) return;
    const int db = gid / N_CONST;
    const int q  = gid - db * N_CONST;

    float best = CUDART_INF_F;
    int   bi   = 0;
    #pragma unroll
    for (int s = 0; s < RSLICES; s++) {
        long e = ((long)db * RSLICES + s) * N_CONST + q;
        float v = g_pbest[e];
        int  id = g_pidx[e];
        if (v < best) { best = v; bi = id; }   // ascending slices => first-min tie-break
    }
    g_idx[gid] = bi;
    atomicAdd(&g_cnt[db * N_CONST + bi], 1);
}

__global__ __launch_bounds__(FIN_TPB) void finalize_partial(const float* __restrict__ gts,
                                                            const float* __restrict__ preds) {
    __shared__ float ssum[FIN_TPB];
    float acc = 0.0f;
    const int e0 = blockIdx.x * FIN_EPB;

    #pragma unroll
    for (int i = 0; i < FIN_EPB / FIN_TPB; i++) {
        int e = e0 + i * FIN_TPB + threadIdx.x;
        int db = e / N_CONST;
        int q  = e - db * N_CONST;
        int b  = db & (B_CONST - 1);
        int dir = db >> 2;
        const float* qptr = (dir == 0) ? gts : preds;
        const float* rptr = (dir == 0) ? preds : gts;
        const float* qb = qptr + (long)b * N_CONST * 3;
        const float* rb = rptr + (long)b * N_CONST * 3;

        int id = g_idx[e];
        float dx = qb[3 * q + 0] - rb[3 * id + 0];
        float dy = qb[3 * q + 1] - rb[3 * id + 1];
        float dz = qb[3 * q + 2] - rb[3 * id + 2];
        float d  = dx * dx + dy * dy + dz * dz;
        float c  = (float)g_cnt[db * N_CONST + id];
        acc += 1.0f - expf(-d) / (c + 1e-6f);   // ALPHA=1, N_LAMBDA=1, frac=1
    }

    ssum[threadIdx.x] = acc;
    __syncthreads();
    for (int off = FIN_TPB / 2; off > 0; off >>= 1) {
        if (threadIdx.x < off) ssum[threadIdx.x] += ssum[threadIdx.x + off];
        __syncthreads();
    }
    if (threadIdx.x == 0) g_part[blockIdx.x] = ssum[0];
}

__global__ void finalize_final(float* __restrict__ out) {
    int b = threadIdx.x;
    if (b >= B_CONST) return;
    float s = 0.0f;
    #pragma unroll
    for (int dir = 0; dir < 2; dir++) {
        int db = dir * B_CONST + b;
        #pragma unroll
        for (int c = 0; c < N_CONST / FIN_EPB; c++)
            s += g_part[db * (N_CONST / FIN_EPB) + c];
    }
    out[b] = s / (2.0f * (float)N_CONST);
}

extern "C" void kernel_launch(void* const* d_in, const int* in_sizes, int n_in,
                              void* d_out, int out_size) {
    const float* gts   = (const float*)d_in[0];
    const float* preds = (const float*)d_in[1];
    float* out = (float*)d_out;

    cudaFuncSetAttribute(nn_kernel, cudaFuncAttributeMaxDynamicSharedMemorySize, SMEM_BYTES);

    zero_kernel<<<(2 * B_CONST * N_CONST + 255) / 256, 256>>>();
    nn_kernel<<<dim3(QCHUNKS, RSLICES, 2 * B_CONST), TPB, SMEM_BYTES>>>(gts, preds);
    merge_kernel<<<(2 * B_CONST * N_CONST + 255) / 256, 256>>>();
    finalize_partial<<<FIN_BLOCKS, FIN_TPB>>>(gts, preds);
    finalize_final<<<1, 32>>>(out);
}

// round 7
// speedup vs baseline: 1.8284x; 1.1476x over previous
#include <cuda_runtime.h>
#include <math_constants.h>

// Density-aware Chamfer loss, B=4, N=8192, 3D fp32.
// R2 skeleton (whole ref cloud in 128KB smem, monolithic, occ 1) with ONE
// lever: halve LDS per combo. TPB=128, QPT=4 => 512 queries/CTA (grid still
// 16x8=128 CTAs), 16 LDS.128 per unroll body now serve 1024 combos.
// No launch_bounds reg cap (occ 1 -> up to 255 regs, no spills).
//  zero_kernel      : clear counts
//  nn_kernel        : packed fma.rn.f32x2; group-min (32) + winning-group
//                     bit-exact rescan; g_idx + histogram atomics inline.
//  finalize_partial : 64-block gather/exp/weight partial sums
//  finalize_final   : fixed-order merge -> out[b]

#define B_CONST   4
#define N_CONST   8192
#define TPB       128
#define QPT       4
#define QPC       (TPB * QPT)          // 512 queries / CTA
#define QCHUNKS   (N_CONST / QPC)      // 16
#define GROUP     32
#define JPG       (GROUP / 2)          // 16
#define NGROUPS   (N_CONST / GROUP)    // 256
#define SMEM_BYTES (N_CONST * 4 * sizeof(float))   // 131072

#define FIN_TPB   256
#define FIN_EPB   1024
#define FIN_BLOCKS (2 * B_CONST * N_CONST / FIN_EPB)  // 64

__device__ int   g_idx [2 * B_CONST * N_CONST];
__device__ int   g_cnt [2 * B_CONST * N_CONST];
__device__ float g_part[FIN_BLOCKS];

__global__ void zero_kernel() {
    int gid = blockIdx.x * blockDim.x + threadIdx.x;
    if (gid < 2 * B_CONST * N_CONST) g_cnt[gid] = 0;
}

// db = dir*B + b.  dir 0: queries = gts, refs = preds. dir 1: swapped.
__global__ __launch_bounds__(TPB, 1) void nn_kernel(const float* __restrict__ gts,
                                                    const float* __restrict__ preds) {
    extern __shared__ float s_tile[];   // jj*8 -> rx0 rx1 ry0 ry1 rz0 rz1 rw0 rw1

    const int db  = blockIdx.y;
    const int b   = db & (B_CONST - 1);
    const int dir = db >> 2;
    const float* __restrict__ qptr = (dir == 0) ? gts : preds;
    const float* __restrict__ rptr = (dir == 0) ? preds : gts;

    // ---- load whole ref cloud into interleaved smem ----
    const float* rbase = rptr + (long)b * N_CONST * 3;
    for (int j = threadIdx.x; j < N_CONST; j += TPB) {
        float x = rbase[3 * j + 0];
        float y = rbase[3 * j + 1];
        float z = rbase[3 * j + 2];
        int jj = j >> 1, h = j & 1;
        float* p = s_tile + jj * 8;
        p[0 + h] = x;
        p[2 + h] = y;
        p[4 + h] = z;
        p[6 + h] = x * x + y * y + z * z;
    }
    __syncthreads();

    // ---- per-thread queries: packed-duplicated (-2*q) ----
    const int q0 = blockIdx.x * QPC + threadIdx.x;
    const float* qbase = qptr + (long)b * N_CONST * 3;

    float qxs[QPT], qys[QPT], qzs[QPT];
    unsigned long long qx2[QPT], qy2[QPT], qz2[QPT];
    float best[QPT];
    int   gidw[QPT];
    float minE[QPT], minO[QPT];

    #pragma unroll
    for (int k = 0; k < QPT; k++) {
        int q = q0 + k * TPB;
        qxs[k] = -2.0f * qbase[3 * q + 0];
        qys[k] = -2.0f * qbase[3 * q + 1];
        qzs[k] = -2.0f * qbase[3 * q + 2];
        asm("mov.b64 %0, {%1, %1};" : "=l"(qx2[k]) : "f"(qxs[k]));
        asm("mov.b64 %0, {%1, %1};" : "=l"(qy2[k]) : "f"(qys[k]));
        asm("mov.b64 %0, {%1, %1};" : "=l"(qz2[k]) : "f"(qzs[k]));
        best[k] = CUDART_INF_F;
        gidw[k] = 0;
        minE[k] = CUDART_INF_F;
        minO[k] = CUDART_INF_F;
    }

    // ---- main scan: groups of 32 refs, packed over j-pairs ----
    for (int g = 0; g < NGROUPS; g++) {
        const float* gb = s_tile + g * JPG * 8;
        #pragma unroll 8
        for (int jj = 0; jj < JPG; jj++) {
            ulonglong2 A  = *(const ulonglong2*)(gb + jj * 8);      // {rx2, ry2}
            ulonglong2 Bv = *(const ulonglong2*)(gb + jj * 8 + 4);  // {rz2, rw2}
            #pragma unroll
            for (int k = 0; k < QPT; k++) {
                float tlo, thi;
                asm("{\n\t"
                    ".reg .b64 t;\n\t"
                    "fma.rn.f32x2 t, %2, %3, %4;\n\t"
                    "fma.rn.f32x2 t, %5, %6, t;\n\t"
                    "fma.rn.f32x2 t, %7, %8, t;\n\t"
                    "mov.b64 {%0, %1}, t;\n\t"
                    "}"
                    : "=f"(tlo), "=f"(thi)
                    : "l"(qx2[k]), "l"(A.x), "l"(Bv.y),
                      "l"(qy2[k]), "l"(A.y),
                      "l"(qz2[k]), "l"(Bv.x));
                minE[k] = fminf(minE[k], tlo);
                minO[k] = fminf(minO[k], thi);
            }
        }
        #pragma unroll
        for (int k = 0; k < QPT; k++) {
            float m = fminf(minE[k], minO[k]);
            if (m < best[k]) { best[k] = m; gidw[k] = g; }  // strict <: earliest group wins
            minE[k] = CUDART_INF_F;
            minO[k] = CUDART_INF_F;
        }
    }

    // ---- rescan winning group: bit-exact recompute, first index wins ----
    #pragma unroll
    for (int k = 0; k < QPT; k++) {
        const int base = gidw[k] * GROUP;
        int idx = 0x7fffffff;
        #pragma unroll 8
        for (int j = 0; j < GROUP; j++) {
            int jj = (base + j) >> 1, h = (base + j) & 1;
            const float* p = s_tile + jj * 8;
            float t = fmaf(qxs[k], p[0 + h], p[6 + h]);
            t = fmaf(qys[k], p[2 + h], t);
            t = fmaf(qzs[k], p[4 + h], t);
            if (t == best[k]) idx = min(idx, base + j);
        }
        int q = q0 + k * TPB;
        g_idx[db * N_CONST + q] = idx;
        atomicAdd(&g_cnt[db * N_CONST + idx], 1);
    }
}

__global__ __launch_bounds__(FIN_TPB) void finalize_partial(const float* __restrict__ gts,
                                                            const float* __restrict__ preds) {
    __shared__ float ssum[FIN_TPB];
    float acc = 0.0f;
    const int e0 = blockIdx.x * FIN_EPB;

    #pragma unroll
    for (int i = 0; i < FIN_EPB / FIN_TPB; i++) {
        int e = e0 + i * FIN_TPB + threadIdx.x;
        int db = e / N_CONST;
        int q  = e - db * N_CONST;
        int b  = db & (B_CONST - 1);
        int dir = db >> 2;
        const float* qptr = (dir == 0) ? gts : preds;
        const float* rptr = (dir == 0) ? preds : gts;
        const float* qb = qptr + (long)b * N_CONST * 3;
        const float* rb = rptr + (long)b * N_CONST * 3;

        int id = g_idx[e];
        float dx = qb[3 * q + 0] - rb[3 * id + 0];
        float dy = qb[3 * q + 1] - rb[3 * id + 1];
        float dz = qb[3 * q + 2] - rb[3 * id + 2];
        float d  = dx * dx + dy * dy + dz * dz;
        float c  = (float)g_cnt[db * N_CONST + id];
        acc += 1.0f - expf(-d) / (c + 1e-6f);   // ALPHA=1, N_LAMBDA=1, frac=1
    }

    ssum[threadIdx.x] = acc;
    __syncthreads();
    for (int off = FIN_TPB / 2; off > 0; off >>= 1) {
        if (threadIdx.x < off) ssum[threadIdx.x] += ssum[threadIdx.x + off];
        __syncthreads();
    }
    if (threadIdx.x == 0) g_part[blockIdx.x] = ssum[0];
}

__global__ void finalize_final(float* __restrict__ out) {
    int b = threadIdx.x;
    if (b >= B_CONST) return;
    float s = 0.0f;
    #pragma unroll
    for (int dir = 0; dir < 2; dir++) {
        int db = dir * B_CONST + b;
        #pragma unroll
        for (int c = 0; c < N_CONST / FIN_EPB; c++)
            s += g_part[db * (N_CONST / FIN_EPB) + c];
    }
    out[b] = s / (2.0f * (float)N_CONST);
}

extern "C" void kernel_launch(void* const* d_in, const int* in_sizes, int n_in,
                              void* d_out, int out_size) {
    const float* gts   = (const float*)d_in[0];
    const float* preds = (const float*)d_in[1];
    float* out = (float*)d_out;

    cudaFuncSetAttribute(nn_kernel, cudaFuncAttributeMaxDynamicSharedMemorySize, SMEM_BYTES);

    zero_kernel<<<(2 * B_CONST * N_CONST + 255) / 256, 256>>>();
    nn_kernel<<<dim3(QCHUNKS, 2 * B_CONST), TPB, SMEM_BYTES>>>(gts, preds);
    finalize_partial<<<FIN_BLOCKS, FIN_TPB>>>(gts, preds);
    finalize_final<<<1, 32>>>(out);
}